// round 15
// baseline (speedup 1.0000x reference)
#include <cuda_runtime.h>
#include <cuda_fp16.h>
#include <cuda_bf16.h>
#include <cstdint>

// Problem constants (fixed by reference)
#define BB 32
#define TT 256
#define CC 512
#define LL 25
#define CC2 (CC / 2)        // 256 half2 per row
#define CSPLIT 8            // c-slices for pvam (32 half2 each)

// Scratch in device globals (no allocations allowed in kernel_launch)
__device__ __half g_wfh[BB * TT * CC];               // 8 MB: post-FC features (fp16)
__device__ float  g_scores[BB * LL * TT];            // 0.8 MB: logits

// ---------------------------------------------------------------------------
__device__ __forceinline__ __half2 htanh2(__half2 x) {
    uint32_t xu = *(uint32_t*)&x, yu;
    asm("tanh.approx.f16x2 %0, %1;" : "=r"(yu) : "r"(xu));
    return *(__half2*)&yu;
}
__device__ __forceinline__ __half2 packh2(float lo, float hi) {
    return __float22half2_rn(make_float2(lo, hi));
}

// ---------------------------------------------------------------------------
// Kernel A: wf[m,n] = sum_k X[m,k]*W[n,k] + bias[n], stored as fp16.
// fp16 mma m16n8k16, fp32 accum. Block 128x128, BK=32 (16 iterations),
// double-buffered; loads split in two groups interleaved with the two
// k16 MMA steps so each group's L2 latency hides behind 16 MMAs.
// Rows padded to 56 halves (28-word stride): frag LDS bank = (28g+tg)%32,
// all 32 lanes distinct -> conflict-free (same for STS uint2).
// ---------------------------------------------------------------------------
#define BKK  32
#define PROW 56                 // halves per row (32 data + 24 pad)
#define BUFH (128 * PROW)       // halves per buffer per matrix (7168)
#define GEMM_SMEM (4 * BUFH * 2)  // bytes: 2 bufs x (A+B) = 57344

__global__ __launch_bounds__(256, 2) void wf_gemm_fp16(
    const float* __restrict__ X,     // [8192, 512]
    const float* __restrict__ W,     // [512, 512] (row n, col k)
    const float* __restrict__ bias)  // [512]
{
    extern __shared__ __half smh[];
    // layout: A0 | A1 | B0 | B1, each BUFH halves

    const int tid  = threadIdx.x;
    const int lane = tid & 31;
    const int warp = tid >> 5;
    const int g    = lane >> 2;          // 0..7
    const int tg   = lane & 3;           // 0..3
    const int wm   = (warp >> 2) << 6;   // 0, 64
    const int wn   = (warp & 3) << 5;    // 0, 32, 64, 96

    const int m0 = blockIdx.y << 7;
    const int n0 = blockIdx.x << 7;

    const int lr  = tid >> 2;            // 0..63
    const int lc4 = (tid & 3) << 2;      // 0, 4, 8, 12 (fp32 col offset)

    const float* Ag = X + (m0 + lr) * CC + lc4;
    const float* Bg = W + (n0 + lr) * CC + lc4;

    float acc[4][4][4];
#pragma unroll
    for (int mt = 0; mt < 4; mt++)
#pragma unroll
        for (int nt = 0; nt < 4; nt++)
#pragma unroll
            for (int i = 0; i < 4; i++) acc[mt][nt][i] = 0.f;

    // convert float4 -> 4 halves, store as uint2
#define CVT_STS(dstp, v)                                                      \
    do {                                                                      \
        __half2 h0 = __float22half2_rn(make_float2((v).x, (v).y));            \
        __half2 h1 = __float22half2_rn(make_float2((v).z, (v).w));            \
        *(uint2*)(dstp) = make_uint2(*(uint32_t*)&h0, *(uint32_t*)&h1);       \
    } while (0)

    // group load: 4 float4 (A rows lr, lr+64; B rows lr, lr+64) at col k0+lc4
#define LDG_GRP(va0, va1, vb0, vb1, K0)                                       \
    do {                                                                      \
        va0 = *(const float4*)(Ag + (K0));                                    \
        va1 = *(const float4*)(Ag + 64 * CC + (K0));                          \
        vb0 = *(const float4*)(Bg + (K0));                                    \
        vb1 = *(const float4*)(Bg + 64 * CC + (K0));                          \
    } while (0)

    // group store into buffer s at k-offset KOFF (halves)
#define STS_GRP(va0, va1, vb0, vb1, S, KOFF)                                  \
    do {                                                                      \
        __half* Ab = smh + (S) * BUFH;                                        \
        __half* Bb = smh + (2 + (S)) * BUFH;                                  \
        CVT_STS(Ab + lr * PROW + (KOFF) + lc4, va0);                          \
        CVT_STS(Ab + (lr + 64) * PROW + (KOFF) + lc4, va1);                   \
        CVT_STS(Bb + lr * PROW + (KOFF) + lc4, vb0);                          \
        CVT_STS(Bb + (lr + 64) * PROW + (KOFF) + lc4, vb1);                   \
    } while (0)

    // one k16 MMA step from buffer S at k-offset KK (halves)
#define MMA_STEP(S, KK)                                                       \
    do {                                                                      \
        const __half* Ab = smh + (S) * BUFH;                                  \
        const __half* Bb = smh + (2 + (S)) * BUFH;                            \
        uint32_t af[4][4], bf[4][2];                                          \
        _Pragma("unroll")                                                     \
        for (int mt = 0; mt < 4; mt++) {                                      \
            const int r = wm + (mt << 4) + g;                                 \
            af[mt][0] = *(const uint32_t*)&Ab[r * PROW + (KK) + 2 * tg];      \
            af[mt][1] = *(const uint32_t*)&Ab[(r + 8) * PROW + (KK) + 2 * tg];\
            af[mt][2] = *(const uint32_t*)&Ab[r * PROW + (KK) + 2 * tg + 8];  \
            af[mt][3] = *(const uint32_t*)&Ab[(r + 8) * PROW + (KK) + 2 * tg + 8];\
        }                                                                     \
        _Pragma("unroll")                                                     \
        for (int nt = 0; nt < 4; nt++) {                                      \
            const int r = wn + (nt << 3) + g;                                 \
            bf[nt][0] = *(const uint32_t*)&Bb[r * PROW + (KK) + 2 * tg];      \
            bf[nt][1] = *(const uint32_t*)&Bb[r * PROW + (KK) + 2 * tg + 8];  \
        }                                                                     \
        _Pragma("unroll")                                                     \
        for (int mt = 0; mt < 4; mt++)                                        \
            _Pragma("unroll")                                                 \
            for (int nt = 0; nt < 4; nt++) {                                  \
                asm volatile(                                                 \
                    "mma.sync.aligned.m16n8k16.row.col.f32.f16.f16.f32 "      \
                    "{%0,%1,%2,%3}, {%4,%5,%6,%7}, {%8,%9}, {%0,%1,%2,%3};"   \
                    : "+f"(acc[mt][nt][0]), "+f"(acc[mt][nt][1]),             \
                      "+f"(acc[mt][nt][2]), "+f"(acc[mt][nt][3])              \
                    : "r"(af[mt][0]), "r"(af[mt][1]),                         \
                      "r"(af[mt][2]), "r"(af[mt][3]),                         \
                      "r"(bf[nt][0]), "r"(bf[nt][1]));                        \
            }                                                                 \
    } while (0)

    float4 a0, a1, b0, b1;

    // prologue: fill buffer 0 (both k-halves)
    LDG_GRP(a0, a1, b0, b1, 0);
    STS_GRP(a0, a1, b0, b1, 0, 0);
    LDG_GRP(a0, a1, b0, b1, 16);
    STS_GRP(a0, a1, b0, b1, 0, 16);
    __syncthreads();

    int s = 0;
    for (int it = 0; it < 16; ++it) {
        const int ns = s ^ 1;
        const int k0 = (it + 1) << 5;        // next tile base k
        if (it < 15) LDG_GRP(a0, a1, b0, b1, k0);
        MMA_STEP(s, 0);
        if (it < 15) {
            STS_GRP(a0, a1, b0, b1, ns, 0);
            LDG_GRP(a0, a1, b0, b1, k0 + 16);
        }
        MMA_STEP(s, 16);
        if (it < 15) {
            STS_GRP(a0, a1, b0, b1, ns, 16);
            __syncthreads();
            s = ns;
        }
    }

    // Epilogue: add bias, convert to fp16, store.
#pragma unroll
    for (int nt = 0; nt < 4; nt++) {
        const int n = n0 + wn + (nt << 3) + (tg << 1);
        const float b0v = bias[n];
        const float b1v = bias[n + 1];
#pragma unroll
        for (int mt = 0; mt < 4; mt++) {
            const int m = m0 + wm + (mt << 4) + g;
            __half2 h0 = packh2(acc[mt][nt][0] + b0v, acc[mt][nt][1] + b1v);
            __half2 h1 = packh2(acc[mt][nt][2] + b0v, acc[mt][nt][3] + b1v);
            *(__half2*)&g_wfh[m * CC + n]       = h0;
            *(__half2*)&g_wfh[(m + 8) * CC + n] = h1;
        }
    }
#undef MMA_STEP
#undef STS_GRP
#undef LDG_GRP
#undef CVT_STS
}

// ---------------------------------------------------------------------------
// Kernel B1: scores[b,l,t] (unchanged — control)
// ---------------------------------------------------------------------------
__global__ __launch_bounds__(256) void scores_kernel(
    const float* __restrict__ pos_emb,   // [25, 512]
    const float* __restrict__ atten_w,   // [512]
    const float* __restrict__ atten_b)   // [1]
{
    const int warp = threadIdx.x >> 5;
    const int lane = threadIdx.x & 31;
    const int b = blockIdx.y;
    const int t0 = blockIdx.x * 32 + warp * 4;

    const float4* awr = (const float4*)atten_w;

    __half2 wfh[4][8];
    float4 aw4[4];
#pragma unroll
    for (int r = 0; r < 4; r++) {
        const uint2* wfr = (const uint2*)(g_wfh + (b * TT + t0 + r) * CC);
#pragma unroll
        for (int i = 0; i < 4; i++) {
            uint2 u = wfr[lane + 32 * i];
            wfh[r][2 * i]     = *(__half2*)&u.x;
            wfh[r][2 * i + 1] = *(__half2*)&u.y;
        }
    }
#pragma unroll
    for (int i = 0; i < 4; i++) aw4[i] = awr[lane + 32 * i];
    const float bsc = atten_b[0];

#pragma unroll 2
    for (int l = 0; l < LL; l++) {
        const float4* pr = (const float4*)(pos_emb + l * CC);
        float acc0 = 0.f, acc1 = 0.f, acc2 = 0.f, acc3 = 0.f;
#pragma unroll
        for (int i = 0; i < 4; i++) {
            float4 p = __ldg(&pr[lane + 32 * i]);
            __half2 p01 = packh2(p.x, p.y);
            __half2 p23 = packh2(p.z, p.w);

            __half2 tA0 = htanh2(__hadd2(wfh[0][2 * i], p01));
            __half2 tA1 = htanh2(__hadd2(wfh[0][2 * i + 1], p23));
            __half2 tB0 = htanh2(__hadd2(wfh[1][2 * i], p01));
            __half2 tB1 = htanh2(__hadd2(wfh[1][2 * i + 1], p23));
            __half2 tC0 = htanh2(__hadd2(wfh[2][2 * i], p01));
            __half2 tC1 = htanh2(__hadd2(wfh[2][2 * i + 1], p23));
            __half2 tD0 = htanh2(__hadd2(wfh[3][2 * i], p01));
            __half2 tD1 = htanh2(__hadd2(wfh[3][2 * i + 1], p23));

            acc0 = fmaf(__low2float(tA0),  aw4[i].x, acc0);
            acc0 = fmaf(__high2float(tA0), aw4[i].y, acc0);
            acc0 = fmaf(__low2float(tA1),  aw4[i].z, acc0);
            acc0 = fmaf(__high2float(tA1), aw4[i].w, acc0);
            acc1 = fmaf(__low2float(tB0),  aw4[i].x, acc1);
            acc1 = fmaf(__high2float(tB0), aw4[i].y, acc1);
            acc1 = fmaf(__low2float(tB1),  aw4[i].z, acc1);
            acc1 = fmaf(__high2float(tB1), aw4[i].w, acc1);
            acc2 = fmaf(__low2float(tC0),  aw4[i].x, acc2);
            acc2 = fmaf(__high2float(tC0), aw4[i].y, acc2);
            acc2 = fmaf(__low2float(tC1),  aw4[i].z, acc2);
            acc2 = fmaf(__high2float(tC1), aw4[i].w, acc2);
            acc3 = fmaf(__low2float(tD0),  aw4[i].x, acc3);
            acc3 = fmaf(__high2float(tD0), aw4[i].y, acc3);
            acc3 = fmaf(__low2float(tD1),  aw4[i].z, acc3);
            acc3 = fmaf(__high2float(tD1), aw4[i].w, acc3);
        }
#pragma unroll
        for (int s = 16; s; s >>= 1) {
            acc0 += __shfl_xor_sync(0xffffffffu, acc0, s);
            acc1 += __shfl_xor_sync(0xffffffffu, acc1, s);
            acc2 += __shfl_xor_sync(0xffffffffu, acc2, s);
            acc3 += __shfl_xor_sync(0xffffffffu, acc3, s);
        }
        if (lane == 0) {
            *(float4*)&g_scores[(b * LL + l) * TT + t0] =
                make_float4(acc0 + bsc, acc1 + bsc, acc2 + bsc, acc3 + bsc);
        }
    }
}

// ---------------------------------------------------------------------------
// Kernel B2: softmax + pvam fused (unchanged — control)
// ---------------------------------------------------------------------------
__global__ __launch_bounds__(256) void pvam_kernel(float* __restrict__ out)
{
    extern __shared__ float sm[];
    float*  at  = sm;                          // [LL*TT] 25.6 KB
    float2* red = (float2*)(sm + LL * TT);     // [8][LL][32] 51.2 KB

    const int tid  = threadIdx.x;
    const int cz   = blockIdx.x;
    const int b    = blockIdx.y;
    const int warp = tid >> 5;
    const int lane = tid & 31;

    const float4* src = (const float4*)(g_scores + b * LL * TT);
    for (int idx = tid; idx < LL * TT / 4; idx += 256)
        ((float4*)at)[idx] = src[idx];
    __syncthreads();

    for (int l = warp; l < LL; l += 8) {
        float v[8];
        float m = -1e30f;
#pragma unroll
        for (int i = 0; i < 8; i++) {
            v[i] = at[l * TT + lane + 32 * i];
            m = fmaxf(m, v[i]);
        }
#pragma unroll
        for (int s = 16; s; s >>= 1) m = fmaxf(m, __shfl_xor_sync(0xffffffffu, m, s));
        float ssum = 0.f;
#pragma unroll
        for (int i = 0; i < 8; i++) {
            v[i] = __expf(v[i] - m);
            ssum += v[i];
        }
#pragma unroll
        for (int s = 16; s; s >>= 1) ssum += __shfl_xor_sync(0xffffffffu, ssum, s);
        float inv = __fdividef(1.f, ssum);
#pragma unroll
        for (int i = 0; i < 8; i++) at[l * TT + lane + 32 * i] = v[i] * inv;
    }
    __syncthreads();

    const int c2 = cz * 32 + lane;
    const int tbase = warp * 32;
    const __half2* wfb = (const __half2*)g_wfh
                       + (size_t)(b * TT + tbase) * CC2 + c2;

    float2 acc[LL];
#pragma unroll
    for (int l = 0; l < LL; l++) acc[l] = make_float2(0.f, 0.f);

    for (int t4 = 0; t4 < 32; t4 += 4) {
        float2 w0 = __half22float2(wfb[(t4 + 0) * CC2]);
        float2 w1 = __half22float2(wfb[(t4 + 1) * CC2]);
        float2 w2 = __half22float2(wfb[(t4 + 2) * CC2]);
        float2 w3 = __half22float2(wfb[(t4 + 3) * CC2]);
#pragma unroll
        for (int l = 0; l < LL; l++) {
            float4 a = *(const float4*)&at[l * TT + tbase + t4];
            float sx = fmaf(a.x, w0.x, acc[l].x);
            float sy = fmaf(a.x, w0.y, acc[l].y);
            sx = fmaf(a.y, w1.x, sx);
            sy = fmaf(a.y, w1.y, sy);
            sx = fmaf(a.z, w2.x, sx);
            sy = fmaf(a.z, w2.y, sy);
            acc[l].x = fmaf(a.w, w3.x, sx);
            acc[l].y = fmaf(a.w, w3.y, sy);
        }
    }

#pragma unroll
    for (int l = 0; l < LL; l++)
        red[(warp * LL + l) * 32 + lane] = acc[l];
    __syncthreads();

    for (int idx = tid; idx < LL * 32; idx += 256) {
        const int l = idx >> 5;
        const int c = idx & 31;
        float2 s = red[(0 * LL + l) * 32 + c];
#pragma unroll
        for (int w = 1; w < 8; w++) {
            float2 v = red[(w * LL + l) * 32 + c];
            s.x += v.x;
            s.y += v.y;
        }
        *(float2*)&out[(size_t)(b * LL + l) * CC + (cz * 32 + c) * 2] = s;
    }
}

// ---------------------------------------------------------------------------
extern "C" void kernel_launch(void* const* d_in, const int* in_sizes, int n_in,
                              void* d_out, int out_size)
{
    const float* word_features = (const float*)d_in[0];  // (32,256,512)
    const float* word_fc_w     = (const float*)d_in[1];  // (512,512)
    const float* word_fc_b     = (const float*)d_in[2];  // (512,)
    const float* pos_emb       = (const float*)d_in[3];  // (25,512)
    const float* atten_w       = (const float*)d_in[4];  // (512,)
    const float* atten_b       = (const float*)d_in[5];  // (1,)
    float* out = (float*)d_out;                          // (32,25,512)

    cudaFuncSetAttribute(wf_gemm_fp16,
                         cudaFuncAttributeMaxDynamicSharedMemorySize, GEMM_SMEM);
    const int pvam_smem = (LL * TT) * 4 + 8 * LL * 32 * 8;  // 76800 B
    cudaFuncSetAttribute(pvam_kernel,
                         cudaFuncAttributeMaxDynamicSharedMemorySize, pvam_smem);

    wf_gemm_fp16<<<dim3(CC / 128, (BB * TT) / 128), 256, GEMM_SMEM>>>(
        word_features, word_fc_w, word_fc_b);
    scores_kernel<<<dim3(TT / 32, BB), 256>>>(pos_emb, atten_w, atten_b);
    pvam_kernel<<<dim3(CSPLIT, BB), 256, pvam_smem>>>(out);
}